// round 3
// baseline (speedup 1.0000x reference)
#include <cuda_runtime.h>
#include <cstdint>

// Problem constants (fixed by the dataset)
#define NUM_AUTHOR 16604
#define NUM_NODES  29059
#define DIM        300
#define NB         32768          // batch of query nodes
#define NE         1048576        // edges
#define KP         928            // padded K (3*300=900 -> 928 = 29*32)
#define NP         304            // padded N for W (300 -> 304)

// Scratch (device globals: allocation-free rule)
__device__ float g_combined[(size_t)NB * KP];   // [B, 928] tf32-rounded, cols 900..927 = 0
__device__ float g_wpad[NP * KP];               // [304, 928] tf32-rounded W1, padded with 0
__device__ int   g_off[NB + 1];                 // segment start offsets

__device__ __forceinline__ float tf32r(float x) {
    uint32_t u;
    asm("cvt.rna.tf32.f32 %0, %1;" : "=r"(u) : "f"(x));
    return __uint_as_float(u);
}

// ---------------------------------------------------------------------------
// Kernel 1: segment offsets via binary search (seg is sorted)
// ---------------------------------------------------------------------------
__global__ void offsets_kernel(const int* __restrict__ seg) {
    int i = blockIdx.x * blockDim.x + threadIdx.x;
    if (i > NB) return;
    int lo = 0, hi = NE;
    while (lo < hi) {
        int mid = (lo + hi) >> 1;
        if (seg[mid] < i) lo = mid + 1; else hi = mid;
    }
    g_off[i] = lo;
}

// ---------------------------------------------------------------------------
// Kernel 2: pad + tf32-round W1 into g_wpad [304 x 928]
// ---------------------------------------------------------------------------
__global__ void padw_kernel(const float* __restrict__ W1) {
    int idx = blockIdx.x * blockDim.x + threadIdx.x;
    if (idx >= NP * KP) return;
    int o = idx / KP, k = idx % KP;
    float v = 0.0f;
    if (o < DIM && k < 3 * DIM) v = W1[o * (3 * DIM) + k];
    g_wpad[idx] = tf32r(v);
}

// ---------------------------------------------------------------------------
// Kernel 3: segment aggregation -> combined = [self | t1 | t2 | 0-pad]
// one block per query node; thread = one embedding dim
// ---------------------------------------------------------------------------
__global__ void __launch_bounds__(320) agg_kernel(
    const int* __restrict__ nodes,
    const int* __restrict__ neighbors,
    const float* __restrict__ emb)
{
    int b   = blockIdx.x;
    int tid = threadIdx.x;
    int start = g_off[b];
    int end   = g_off[b + 1];
    int node  = nodes[b];
    bool selfA = node < NUM_AUTHOR;
    float* cb = g_combined + (size_t)b * KP;

    if (tid < DIM) {
        float selfv = emb[node * DIM + tid];
        float acc1 = 0.f, acc2 = 0.f;
        int c1 = 0;
        int e = start;
        for (; e + 4 <= end; e += 4) {
            int n0 = neighbors[e];
            int n1 = neighbors[e + 1];
            int n2 = neighbors[e + 2];
            int n3 = neighbors[e + 3];
            float v0 = emb[n0 * DIM + tid];
            float v1 = emb[n1 * DIM + tid];
            float v2 = emb[n2 * DIM + tid];
            float v3 = emb[n3 * DIM + tid];
            bool s0 = (n0 < NUM_AUTHOR) == selfA;
            bool s1 = (n1 < NUM_AUTHOR) == selfA;
            bool s2 = (n2 < NUM_AUTHOR) == selfA;
            bool s3 = (n3 < NUM_AUTHOR) == selfA;
            acc1 += s0 ? v0 : 0.f;  acc2 += s0 ? 0.f : v0;  c1 += s0;
            acc1 += s1 ? v1 : 0.f;  acc2 += s1 ? 0.f : v1;  c1 += s1;
            acc1 += s2 ? v2 : 0.f;  acc2 += s2 ? 0.f : v2;  c1 += s2;
            acc1 += s3 ? v3 : 0.f;  acc2 += s3 ? 0.f : v3;  c1 += s3;
        }
        for (; e < end; e++) {
            int n = neighbors[e];
            float v = emb[n * DIM + tid];
            bool s = (n < NUM_AUTHOR) == selfA;
            acc1 += s ? v : 0.f;  acc2 += s ? 0.f : v;  c1 += s;
        }
        int tot = end - start;
        int c2 = tot - c1;
        float t1 = (c1 > 0) ? acc1 / (float)c1 : 1.0f;
        float t2 = (c2 > 0) ? acc2 / (float)c2 : 1.0f;
        __stcs(&cb[tid],            tf32r(selfv));
        __stcs(&cb[DIM + tid],      tf32r(t1));
        __stcs(&cb[2 * DIM + tid],  tf32r(t2));
    }
    if (tid < KP - 3 * DIM) {   // zero-pad cols 900..927
        __stcs(&cb[3 * DIM + tid], 0.0f);
    }
}

// ---------------------------------------------------------------------------
// Kernel 4: GEMM  out[32768,300] = combined[32768,928] @ Wpad^T + b1
// tf32 mma.sync m16n8k8 ; BM=128, BN=64, BK=32 ; 8 warps (4M x 2N)
// grid = (5 N-tiles [x fast -> A shared in L2], 256 M-tiles)
// ---------------------------------------------------------------------------
#define BM 128
#define BN 64
#define BK 32
#define SSTR (BK + 4)   // smem row stride 36: banks = (4*gid + tig) -> conflict-free

__global__ void __launch_bounds__(256) gemm_kernel(
    const float* __restrict__ b1,
    float* __restrict__ out)
{
    __shared__ float As[BM][SSTR];
    __shared__ float Bs[BN][SSTR];

    int bn = blockIdx.x;      // 0..4
    int bm = blockIdx.y;      // 0..255
    int tid  = threadIdx.x;
    int warp = tid >> 5, lane = tid & 31;
    int wm = warp & 3, wn = warp >> 2;
    int gid = lane >> 2, tig = lane & 3;

    const float* Ag = g_combined + (size_t)(bm * BM) * KP;
    const float* Bg = g_wpad + (size_t)(bn * BN) * KP;

    float c[2][4][4];
#pragma unroll
    for (int mt = 0; mt < 2; mt++)
#pragma unroll
        for (int nt = 0; nt < 4; nt++)
#pragma unroll
            for (int i = 0; i < 4; i++) c[mt][nt][i] = 0.f;

    for (int kt = 0; kt < KP / BK; kt++) {
        // load A tile: 128x32 = 1024 float4, 4 per thread
#pragma unroll
        for (int i = 0; i < 4; i++) {
            int lin = tid + i * 256;
            int row = lin >> 3, c4 = lin & 7;
            float4 v = *(const float4*)(Ag + (size_t)row * KP + kt * BK + c4 * 4);
            *(float4*)(&As[row][c4 * 4]) = v;
        }
        // load B tile: 64x32 = 512 float4, 2 per thread
#pragma unroll
        for (int i = 0; i < 2; i++) {
            int lin = tid + i * 256;
            int row = lin >> 3, c4 = lin & 7;
            float4 v = *(const float4*)(Bg + (size_t)row * KP + kt * BK + c4 * 4);
            *(float4*)(&Bs[row][c4 * 4]) = v;
        }
        __syncthreads();

#pragma unroll
        for (int ks = 0; ks < 4; ks++) {
            int k0 = ks * 8;
            uint32_t a[2][4], bfr[4][2];
#pragma unroll
            for (int mt = 0; mt < 2; mt++) {
                int r = wm * 32 + mt * 16 + gid;
                a[mt][0] = __float_as_uint(As[r][k0 + tig]);
                a[mt][1] = __float_as_uint(As[r + 8][k0 + tig]);
                a[mt][2] = __float_as_uint(As[r][k0 + tig + 4]);
                a[mt][3] = __float_as_uint(As[r + 8][k0 + tig + 4]);
            }
#pragma unroll
            for (int nt = 0; nt < 4; nt++) {
                int n = wn * 32 + nt * 8 + gid;
                bfr[nt][0] = __float_as_uint(Bs[n][k0 + tig]);
                bfr[nt][1] = __float_as_uint(Bs[n][k0 + tig + 4]);
            }
#pragma unroll
            for (int mt = 0; mt < 2; mt++)
#pragma unroll
                for (int nt = 0; nt < 4; nt++) {
                    asm volatile(
                        "mma.sync.aligned.m16n8k8.row.col.f32.tf32.tf32.f32 "
                        "{%0,%1,%2,%3},{%4,%5,%6,%7},{%8,%9},{%0,%1,%2,%3};"
                        : "+f"(c[mt][nt][0]), "+f"(c[mt][nt][1]),
                          "+f"(c[mt][nt][2]), "+f"(c[mt][nt][3])
                        : "r"(a[mt][0]), "r"(a[mt][1]), "r"(a[mt][2]), "r"(a[mt][3]),
                          "r"(bfr[nt][0]), "r"(bfr[nt][1]));
                }
        }
        __syncthreads();
    }

    // epilogue: +b1, store (guard N=300)
#pragma unroll
    for (int mt = 0; mt < 2; mt++) {
#pragma unroll
        for (int nt = 0; nt < 4; nt++) {
            int gn = bn * BN + wn * 32 + nt * 8 + tig * 2;
            if (gn < DIM) {
                float bb0 = b1[gn], bb1 = b1[gn + 1];
                int gm0 = bm * BM + wm * 32 + mt * 16 + gid;
                float2 v0, v1;
                v0.x = c[mt][nt][0] + bb0;  v0.y = c[mt][nt][1] + bb1;
                v1.x = c[mt][nt][2] + bb0;  v1.y = c[mt][nt][3] + bb1;
                *(float2*)(out + (size_t)gm0 * DIM + gn) = v0;
                *(float2*)(out + (size_t)(gm0 + 8) * DIM + gn) = v1;
            }
        }
    }
}

// ---------------------------------------------------------------------------
extern "C" void kernel_launch(void* const* d_in, const int* in_sizes, int n_in,
                              void* d_out, int out_size) {
    const int*   nodes     = (const int*)d_in[0];
    const int*   seg       = (const int*)d_in[1];
    const int*   neighbors = (const int*)d_in[2];
    const float* emb       = (const float*)d_in[3];
    const float* W1        = (const float*)d_in[4];
    const float* b1        = (const float*)d_in[5];
    float*       out       = (float*)d_out;

    offsets_kernel<<<(NB + 1 + 255) / 256, 256>>>(seg);
    padw_kernel<<<(NP * KP + 255) / 256, 256>>>(W1);
    agg_kernel<<<NB, 320>>>(nodes, neighbors, emb);
    dim3 grid(5, NB / BM);   // x = N-tile (fast) so N-tiles of one M-tile share A in L2
    gemm_kernel<<<grid, 256>>>(b1, out);
}

// round 4
// speedup vs baseline: 1.1696x; 1.1696x over previous
#include <cuda_runtime.h>
#include <cuda_fp16.h>
#include <cstdint>

// Problem constants
#define NUM_AUTHOR 16604
#define NUM_NODES  29059
#define DIM        300
#define NB         32768
#define NE         1048576

// GEMM padding: proj = emb[29059,300] @ Wcat[960,300]^T
#define MPAD  29184        // 228 * 128
#define KA    320          // K padded 300 -> 320 (10 x BK=32)
#define NPADC 960          // 3 sections x 320 cols (each section 64B-aligned in fp16)
#define PSTR  960          // proj row stride (halves)

// Scratch (device globals; allocation-free rule)
__device__ float  g_apad[(size_t)MPAD * KA];     // tf32-rounded, zero-padded emb
__device__ float  g_wcat[(size_t)NPADC * KA];    // tf32-rounded, remapped W1
__device__ __half g_proj[(size_t)MPAD * PSTR];   // projected table, fp16 (56 MB, L2-resident)
__device__ float  g_rsB[DIM];                    // rowsum of Wb (empty-type-1 fallback)
__device__ float  g_rsC[DIM];                    // rowsum of Wc (empty-type-2 fallback)
__device__ int    g_off[NB + 1];

__device__ __forceinline__ float tf32r(float x) {
    uint32_t u;
    asm("cvt.rna.tf32.f32 %0, %1;" : "=r"(u) : "f"(x));
    return __uint_as_float(u);
}

__device__ __forceinline__ void cp_async16(void* sdst, const void* gsrc) {
    uint32_t d = (uint32_t)__cvta_generic_to_shared(sdst);
    asm volatile("cp.async.cg.shared.global [%0], [%1], 16;" :: "r"(d), "l"(gsrc));
}
#define CP_COMMIT() asm volatile("cp.async.commit_group;")
#define CP_WAIT(n)  asm volatile("cp.async.wait_group %0;" :: "n"(n))

// ---------------------------------------------------------------------------
// Kernel 1: segment offsets via binary search (seg sorted)
// ---------------------------------------------------------------------------
__global__ void offsets_kernel(const int* __restrict__ seg) {
    int i = blockIdx.x * blockDim.x + threadIdx.x;
    if (i > NB) return;
    int lo = 0, hi = NE;
    while (lo < hi) {
        int mid = (lo + hi) >> 1;
        if (seg[mid] < i) lo = mid + 1; else hi = mid;
    }
    g_off[i] = lo;
}

// ---------------------------------------------------------------------------
// Kernel 2: pad + tf32-round emb into g_apad [MPAD x KA]
// ---------------------------------------------------------------------------
__global__ void apad_kernel(const float* __restrict__ emb) {
    int row = blockIdx.x, k = threadIdx.x;     // grid=MPAD, block=320
    float v = 0.0f;
    if (row < NUM_NODES && k < DIM) v = tf32r(emb[(size_t)row * DIM + k]);
    g_apad[(size_t)row * KA + k] = v;
}

// ---------------------------------------------------------------------------
// Kernel 3: build Wcat [960 x 320]: section s (Wa,Wb,Wc) at rows s*320 + j
//   wcat[s*320+j][k] = W1[j][s*300+k]
// ---------------------------------------------------------------------------
__global__ void wcat_kernel(const float* __restrict__ W1) {
    int c = blockIdx.x, k = threadIdx.x;       // grid=960, block=320
    int sec = c / 320, j = c - sec * 320;
    float v = 0.0f;
    if (j < DIM && k < DIM) v = tf32r(W1[(size_t)j * (3 * DIM) + sec * DIM + k]);
    g_wcat[(size_t)c * KA + k] = v;
}

// ---------------------------------------------------------------------------
// Kernel 4: fallback rowsums: rsB[j] = sum_k W1[j,300+k], rsC for 600+k
// ---------------------------------------------------------------------------
__global__ void rowsum_kernel(const float* __restrict__ W1) {
    int j = threadIdx.x;                        // 1 block x 300
    if (j >= DIM) return;
    float sb = 0.f, sc = 0.f;
    for (int k = 0; k < DIM; k++) {
        sb += W1[(size_t)j * (3 * DIM) + DIM + k];
        sc += W1[(size_t)j * (3 * DIM) + 2 * DIM + k];
    }
    g_rsB[j] = sb;  g_rsC[j] = sc;
}

// ---------------------------------------------------------------------------
// Kernel 5: GEMM  proj[MPAD,960](fp16) = apad[MPAD,320] @ wcat[960,320]^T
// tf32 mma m16n8k8; BM=128, BN=64, BK=32; 4 warps, warp tile 64x32 (mt4,nt4)
// XOR-swizzled smem, cp.async.cg double buffer
// ---------------------------------------------------------------------------
#define BM 128
#define BN 64
#define BK 32
#define NT (KA / BK)   // 10

__device__ __forceinline__ void load_tiles(const float* Ag, const float* Bg,
                                           float (*As)[BK], float (*Bs)[BK],
                                           int kt, int tid) {
#pragma unroll
    for (int i = 0; i < 8; i++) {              // A: 128x32 = 1024 float4
        int lin = tid + i * 128;
        int row = lin >> 3, c4 = lin & 7;
        int col = (c4 * 4) ^ ((row & 7) << 2);
        cp_async16(&As[row][col], Ag + (size_t)row * KA + kt * BK + c4 * 4);
    }
#pragma unroll
    for (int i = 0; i < 4; i++) {              // B: 64x32 = 512 float4
        int lin = tid + i * 128;
        int row = lin >> 3, c4 = lin & 7;
        int col = (c4 * 4) ^ ((row & 7) << 2);
        cp_async16(&Bs[row][col], Bg + (size_t)row * KA + kt * BK + c4 * 4);
    }
}

__global__ void __launch_bounds__(128) proj_gemm_kernel() {
    __shared__ float As[2][BM][BK];
    __shared__ float Bs[2][BN][BK];

    int bn = blockIdx.x;      // 0..14
    int bm = blockIdx.y;      // 0..227
    int tid = threadIdx.x;
    int warp = tid >> 5, lane = tid & 31;
    int wm = warp & 1, wn = warp >> 1;
    int gid = lane >> 2, tig = lane & 3;

    const float* Ag = g_apad + (size_t)(bm * BM) * KA;
    const float* Bg = g_wcat + (size_t)(bn * BN) * KA;

    float c[4][4][4];
#pragma unroll
    for (int mt = 0; mt < 4; mt++)
#pragma unroll
        for (int nt = 0; nt < 4; nt++)
#pragma unroll
            for (int i = 0; i < 4; i++) c[mt][nt][i] = 0.f;

    load_tiles(Ag, Bg, As[0], Bs[0], 0, tid);
    CP_COMMIT();

    for (int kt = 0; kt < NT; kt++) {
        int buf = kt & 1;
        if (kt + 1 < NT) {
            load_tiles(Ag, Bg, As[buf ^ 1], Bs[buf ^ 1], kt + 1, tid);
            CP_COMMIT();
            CP_WAIT(1);
        } else {
            CP_WAIT(0);
        }
        __syncthreads();

#pragma unroll
        for (int ks = 0; ks < 4; ks++) {
            int k0 = ks * 8;
            uint32_t a[4][4], bfr[4][2];
#pragma unroll
            for (int mt = 0; mt < 4; mt++) {
                int r0 = wm * 64 + mt * 16 + gid;
                int x = (r0 & 7) << 2;           // (r0+8)&7 == r0&7
                a[mt][0] = __float_as_uint(As[buf][r0][(k0 + tig) ^ x]);
                a[mt][1] = __float_as_uint(As[buf][r0 + 8][(k0 + tig) ^ x]);
                a[mt][2] = __float_as_uint(As[buf][r0][(k0 + tig + 4) ^ x]);
                a[mt][3] = __float_as_uint(As[buf][r0 + 8][(k0 + tig + 4) ^ x]);
            }
#pragma unroll
            for (int nt = 0; nt < 4; nt++) {
                int n = wn * 32 + nt * 8 + gid;
                int x = (n & 7) << 2;
                bfr[nt][0] = __float_as_uint(Bs[buf][n][(k0 + tig) ^ x]);
                bfr[nt][1] = __float_as_uint(Bs[buf][n][(k0 + tig + 4) ^ x]);
            }
#pragma unroll
            for (int mt = 0; mt < 4; mt++)
#pragma unroll
                for (int nt = 0; nt < 4; nt++) {
                    asm volatile(
                        "mma.sync.aligned.m16n8k8.row.col.f32.tf32.tf32.f32 "
                        "{%0,%1,%2,%3},{%4,%5,%6,%7},{%8,%9},{%0,%1,%2,%3};"
                        : "+f"(c[mt][nt][0]), "+f"(c[mt][nt][1]),
                          "+f"(c[mt][nt][2]), "+f"(c[mt][nt][3])
                        : "r"(a[mt][0]), "r"(a[mt][1]), "r"(a[mt][2]), "r"(a[mt][3]),
                          "r"(bfr[nt][0]), "r"(bfr[nt][1]));
                }
        }
        __syncthreads();
    }

    // Epilogue: fp16 store (no bias here; bias added in agg)
#pragma unroll
    for (int mt = 0; mt < 4; mt++) {
#pragma unroll
        for (int nt = 0; nt < 4; nt++) {
            int gm = bm * BM + wm * 64 + mt * 16 + gid;
            int gn = bn * BN + wn * 32 + nt * 8 + tig * 2;
            __half2 h0 = __floats2half2_rn(c[mt][nt][0], c[mt][nt][1]);
            __half2 h1 = __floats2half2_rn(c[mt][nt][2], c[mt][nt][3]);
            *(__half2*)(g_proj + (size_t)gm * PSTR + gn) = h0;
            *(__half2*)(g_proj + (size_t)(gm + 8) * PSTR + gn) = h1;
        }
    }
}

// ---------------------------------------------------------------------------
// Kernel 6: aggregation over fp16 projected table, writes final out
// block = one query node, 160 threads (thread = 2 dims via half2)
// proj row layout: [projA: 0..299][pad][projB: 320..619][pad][projC: 640..939][pad]
// ---------------------------------------------------------------------------
__global__ void __launch_bounds__(160) agg_kernel(
    const int* __restrict__ nodes,
    const int* __restrict__ neighbors,
    const float* __restrict__ b1,
    float* __restrict__ out)
{
    int b = blockIdx.x;
    int tid = threadIdx.x;
    int start = g_off[b];
    int end   = g_off[b + 1];
    int node  = nodes[b];
    bool selfA = node < NUM_AUTHOR;

    float2 a1 = {0.f, 0.f}, a2 = {0.f, 0.f};
    int c1 = 0;

    int e = start;
    for (; e + 4 <= end; e += 4) {
        int n0 = neighbors[e];
        int n1 = neighbors[e + 1];
        int n2 = neighbors[e + 2];
        int n3 = neighbors[e + 3];
        bool s0 = (n0 < NUM_AUTHOR) == selfA;
        bool s1 = (n1 < NUM_AUTHOR) == selfA;
        bool s2 = (n2 < NUM_AUTHOR) == selfA;
        bool s3 = (n3 < NUM_AUTHOR) == selfA;
        __half2 h0 = *((const __half2*)(g_proj + (size_t)n0 * PSTR + (s0 ? 320 : 640)) + tid);
        __half2 h1 = *((const __half2*)(g_proj + (size_t)n1 * PSTR + (s1 ? 320 : 640)) + tid);
        __half2 h2 = *((const __half2*)(g_proj + (size_t)n2 * PSTR + (s2 ? 320 : 640)) + tid);
        __half2 h3 = *((const __half2*)(g_proj + (size_t)n3 * PSTR + (s3 ? 320 : 640)) + tid);
        float2 f0 = __half22float2(h0);
        float2 f1 = __half22float2(h1);
        float2 f2 = __half22float2(h2);
        float2 f3 = __half22float2(h3);
        if (s0) { a1.x += f0.x; a1.y += f0.y; } else { a2.x += f0.x; a2.y += f0.y; }
        if (s1) { a1.x += f1.x; a1.y += f1.y; } else { a2.x += f1.x; a2.y += f1.y; }
        if (s2) { a1.x += f2.x; a1.y += f2.y; } else { a2.x += f2.x; a2.y += f2.y; }
        if (s3) { a1.x += f3.x; a1.y += f3.y; } else { a2.x += f3.x; a2.y += f3.y; }
        c1 += (int)s0 + (int)s1 + (int)s2 + (int)s3;
    }
    for (; e < end; e++) {
        int n = neighbors[e];
        bool s = (n < NUM_AUTHOR) == selfA;
        __half2 h = *((const __half2*)(g_proj + (size_t)n * PSTR + (s ? 320 : 640)) + tid);
        float2 f = __half22float2(h);
        if (s) { a1.x += f.x; a1.y += f.y; } else { a2.x += f.x; a2.y += f.y; }
        c1 += (int)s;
    }

    if (tid * 2 < DIM) {
        int tot = end - start;
        int c2 = tot - c1;
        float2 t1, t2;
        if (c1 > 0) { float r = 1.0f / (float)c1; t1.x = a1.x * r; t1.y = a1.y * r; }
        else        { t1.x = g_rsB[2 * tid];      t1.y = g_rsB[2 * tid + 1]; }
        if (c2 > 0) { float r = 1.0f / (float)c2; t2.x = a2.x * r; t2.y = a2.y * r; }
        else        { t2.x = g_rsC[2 * tid];      t2.y = g_rsC[2 * tid + 1]; }

        __half2 sh = *((const __half2*)(g_proj + (size_t)node * PSTR) + tid);
        float2 sf = __half22float2(sh);
        float2 bb = *(const float2*)(b1 + 2 * tid);
        float2 o;
        o.x = sf.x + t1.x + t2.x + bb.x;
        o.y = sf.y + t1.y + t2.y + bb.y;
        *(float2*)(out + (size_t)b * DIM + 2 * tid) = o;
    }
}

// ---------------------------------------------------------------------------
extern "C" void kernel_launch(void* const* d_in, const int* in_sizes, int n_in,
                              void* d_out, int out_size) {
    const int*   nodes     = (const int*)d_in[0];
    const int*   seg       = (const int*)d_in[1];
    const int*   neighbors = (const int*)d_in[2];
    const float* emb       = (const float*)d_in[3];
    const float* W1        = (const float*)d_in[4];
    const float* b1        = (const float*)d_in[5];
    float*       out       = (float*)d_out;

    offsets_kernel<<<(NB + 1 + 255) / 256, 256>>>(seg);
    apad_kernel<<<MPAD, 320>>>(emb);
    wcat_kernel<<<NPADC, 320>>>(W1);
    rowsum_kernel<<<1, 320>>>(W1);
    dim3 ggrid(NPADC / BN, MPAD / BM);   // (15, 228), x-fast shares A via L2
    proj_gemm_kernel<<<ggrid, 128>>>();
    agg_kernel<<<NB, 160>>>(nodes, neighbors, b1, out);
}

// round 5
// speedup vs baseline: 1.2087x; 1.0335x over previous
#include <cuda_runtime.h>
#include <cuda_fp16.h>
#include <cstdint>

// Problem constants
#define NUM_AUTHOR 16604
#define NUM_NODES  29059
#define DIM        300
#define NB         32768
#define NE         1048576

// GEMM padding: proj = emb[29059,300] @ Wcat[960,300]^T
#define MPAD  29184        // 228 * 128
#define KA    320          // K padded 300 -> 320 (10 x BK=32)
#define NPADC 960          // 3 sections x 320 cols (each section 64B-aligned in fp16)
#define PSTR  960          // proj row stride (halves)

// Scratch (device globals; allocation-free rule)
__device__ float  g_apad[(size_t)MPAD * KA];     // tf32-rounded, zero-padded emb
__device__ float  g_wcat[(size_t)NPADC * KA];    // tf32-rounded, remapped W1
__device__ __half g_proj[(size_t)MPAD * PSTR];   // projected table, fp16 (56 MB, L2-resident)
__device__ float  g_rsB[DIM];                    // rowsum of Wb (empty-type-1 fallback)
__device__ float  g_rsC[DIM];                    // rowsum of Wc (empty-type-2 fallback)
__device__ int    g_off[NB + 1];

__device__ __forceinline__ float tf32r(float x) {
    uint32_t u;
    asm("cvt.rna.tf32.f32 %0, %1;" : "=r"(u) : "f"(x));
    return __uint_as_float(u);
}

__device__ __forceinline__ void cp_async16(void* sdst, const void* gsrc) {
    uint32_t d = (uint32_t)__cvta_generic_to_shared(sdst);
    asm volatile("cp.async.cg.shared.global [%0], [%1], 16;" :: "r"(d), "l"(gsrc));
}
#define CP_COMMIT() asm volatile("cp.async.commit_group;")
#define CP_WAIT(n)  asm volatile("cp.async.wait_group %0;" :: "n"(n))

// ---------------------------------------------------------------------------
// Kernel 1: segment offsets via binary search (seg sorted)
// ---------------------------------------------------------------------------
__global__ void offsets_kernel(const int* __restrict__ seg) {
    int i = blockIdx.x * blockDim.x + threadIdx.x;
    if (i > NB) return;
    int lo = 0, hi = NE;
    while (lo < hi) {
        int mid = (lo + hi) >> 1;
        if (seg[mid] < i) lo = mid + 1; else hi = mid;
    }
    g_off[i] = lo;
}

// ---------------------------------------------------------------------------
// Kernel 2: pad + tf32-round emb into g_apad [MPAD x KA]
// ---------------------------------------------------------------------------
__global__ void apad_kernel(const float* __restrict__ emb) {
    int row = blockIdx.x, k = threadIdx.x;     // grid=MPAD, block=320
    float v = 0.0f;
    if (row < NUM_NODES && k < DIM) v = tf32r(emb[(size_t)row * DIM + k]);
    g_apad[(size_t)row * KA + k] = v;
}

// ---------------------------------------------------------------------------
// Kernel 3: build Wcat [960 x 320]: section s (Wa,Wb,Wc) at rows s*320 + j
//   wcat[s*320+j][k] = W1[j][s*300+k]
// ---------------------------------------------------------------------------
__global__ void wcat_kernel(const float* __restrict__ W1) {
    int c = blockIdx.x, k = threadIdx.x;       // grid=960, block=320
    int sec = c / 320, j = c - sec * 320;
    float v = 0.0f;
    if (j < DIM && k < DIM) v = tf32r(W1[(size_t)j * (3 * DIM) + sec * DIM + k]);
    g_wcat[(size_t)c * KA + k] = v;
}

// ---------------------------------------------------------------------------
// Kernel 4: fallback rowsums: rsB[j] = sum_k W1[j,300+k], rsC for 600+k
// ---------------------------------------------------------------------------
__global__ void rowsum_kernel(const float* __restrict__ W1) {
    int j = threadIdx.x;                        // 1 block x 300
    if (j >= DIM) return;
    float sb = 0.f, sc = 0.f;
    for (int k = 0; k < DIM; k++) {
        sb += W1[(size_t)j * (3 * DIM) + DIM + k];
        sc += W1[(size_t)j * (3 * DIM) + 2 * DIM + k];
    }
    g_rsB[j] = sb;  g_rsC[j] = sc;
}

// ---------------------------------------------------------------------------
// Kernel 5: GEMM  proj[MPAD,960](fp16) = apad[MPAD,320] @ wcat[960,320]^T
// tf32 mma m16n8k8; BM=128, BN=64, BK=32; 4 warps, warp tile 64x32 (mt4,nt4)
// XOR-swizzled smem, cp.async.cg double buffer
// ---------------------------------------------------------------------------
#define BM 128
#define BN 64
#define BK 32
#define NT (KA / BK)   // 10

__device__ __forceinline__ void load_tiles(const float* Ag, const float* Bg,
                                           float (*As)[BK], float (*Bs)[BK],
                                           int kt, int tid) {
#pragma unroll
    for (int i = 0; i < 8; i++) {              // A: 128x32 = 1024 float4
        int lin = tid + i * 128;
        int row = lin >> 3, c4 = lin & 7;
        int col = (c4 * 4) ^ ((row & 7) << 2);
        cp_async16(&As[row][col], Ag + (size_t)row * KA + kt * BK + c4 * 4);
    }
#pragma unroll
    for (int i = 0; i < 4; i++) {              // B: 64x32 = 512 float4
        int lin = tid + i * 128;
        int row = lin >> 3, c4 = lin & 7;
        int col = (c4 * 4) ^ ((row & 7) << 2);
        cp_async16(&Bs[row][col], Bg + (size_t)row * KA + kt * BK + c4 * 4);
    }
}

__global__ void __launch_bounds__(128) proj_gemm_kernel() {
    __shared__ float As[2][BM][BK];
    __shared__ float Bs[2][BN][BK];

    int bn = blockIdx.x;      // 0..14
    int bm = blockIdx.y;      // 0..227
    int tid = threadIdx.x;
    int warp = tid >> 5, lane = tid & 31;
    int wm = warp & 1, wn = warp >> 1;
    int gid = lane >> 2, tig = lane & 3;

    const float* Ag = g_apad + (size_t)(bm * BM) * KA;
    const float* Bg = g_wcat + (size_t)(bn * BN) * KA;

    float c[4][4][4];
#pragma unroll
    for (int mt = 0; mt < 4; mt++)
#pragma unroll
        for (int nt = 0; nt < 4; nt++)
#pragma unroll
            for (int i = 0; i < 4; i++) c[mt][nt][i] = 0.f;

    load_tiles(Ag, Bg, As[0], Bs[0], 0, tid);
    CP_COMMIT();

    for (int kt = 0; kt < NT; kt++) {
        int buf = kt & 1;
        if (kt + 1 < NT) {
            load_tiles(Ag, Bg, As[buf ^ 1], Bs[buf ^ 1], kt + 1, tid);
            CP_COMMIT();
            CP_WAIT(1);
        } else {
            CP_WAIT(0);
        }
        __syncthreads();

#pragma unroll
        for (int ks = 0; ks < 4; ks++) {
            int k0 = ks * 8;
            uint32_t a[4][4], bfr[4][2];
#pragma unroll
            for (int mt = 0; mt < 4; mt++) {
                int r0 = wm * 64 + mt * 16 + gid;
                int x = (r0 & 7) << 2;           // (r0+8)&7 == r0&7
                a[mt][0] = __float_as_uint(As[buf][r0][(k0 + tig) ^ x]);
                a[mt][1] = __float_as_uint(As[buf][r0 + 8][(k0 + tig) ^ x]);
                a[mt][2] = __float_as_uint(As[buf][r0][(k0 + tig + 4) ^ x]);
                a[mt][3] = __float_as_uint(As[buf][r0 + 8][(k0 + tig + 4) ^ x]);
            }
#pragma unroll
            for (int nt = 0; nt < 4; nt++) {
                int n = wn * 32 + nt * 8 + gid;
                int x = (n & 7) << 2;
                bfr[nt][0] = __float_as_uint(Bs[buf][n][(k0 + tig) ^ x]);
                bfr[nt][1] = __float_as_uint(Bs[buf][n][(k0 + tig + 4) ^ x]);
            }
#pragma unroll
            for (int mt = 0; mt < 4; mt++)
#pragma unroll
                for (int nt = 0; nt < 4; nt++) {
                    asm volatile(
                        "mma.sync.aligned.m16n8k8.row.col.f32.tf32.tf32.f32 "
                        "{%0,%1,%2,%3},{%4,%5,%6,%7},{%8,%9},{%0,%1,%2,%3};"
                        : "+f"(c[mt][nt][0]), "+f"(c[mt][nt][1]),
                          "+f"(c[mt][nt][2]), "+f"(c[mt][nt][3])
                        : "r"(a[mt][0]), "r"(a[mt][1]), "r"(a[mt][2]), "r"(a[mt][3]),
                          "r"(bfr[nt][0]), "r"(bfr[nt][1]));
                }
        }
        __syncthreads();
    }

    // Epilogue: fp16 store (no bias here; bias added in agg)
#pragma unroll
    for (int mt = 0; mt < 4; mt++) {
#pragma unroll
        for (int nt = 0; nt < 4; nt++) {
            int gm = bm * BM + wm * 64 + mt * 16 + gid;
            int gn = bn * BN + wn * 32 + nt * 8 + tig * 2;
            __half2 h0 = __floats2half2_rn(c[mt][nt][0], c[mt][nt][1]);
            __half2 h1 = __floats2half2_rn(c[mt][nt][2], c[mt][nt][3]);
            *(__half2*)(g_proj + (size_t)gm * PSTR + gn) = h0;
            *(__half2*)(g_proj + (size_t)(gm + 8) * PSTR + gn) = h1;
        }
    }
}

// ---------------------------------------------------------------------------
// Kernel 6: aggregation over fp16 projected table, writes final out
// block = one query node, 160 threads (thread = 2 dims via half2)
// proj row layout: [projA: 0..299][pad][projB: 320..619][pad][projC: 640..939][pad]
// ---------------------------------------------------------------------------
__global__ void __launch_bounds__(160) agg_kernel(
    const int* __restrict__ nodes,
    const int* __restrict__ neighbors,
    const float* __restrict__ b1,
    float* __restrict__ out)
{
    int b = blockIdx.x;
    int tid = threadIdx.x;
    int start = g_off[b];
    int end   = g_off[b + 1];
    int node  = nodes[b];
    bool selfA = node < NUM_AUTHOR;

    float2 a1 = {0.f, 0.f}, a2 = {0.f, 0.f};
    int c1 = 0;

    int e = start;
    for (; e + 4 <= end; e += 4) {
        int n0 = neighbors[e];
        int n1 = neighbors[e + 1];
        int n2 = neighbors[e + 2];
        int n3 = neighbors[e + 3];
        bool s0 = (n0 < NUM_AUTHOR) == selfA;
        bool s1 = (n1 < NUM_AUTHOR) == selfA;
        bool s2 = (n2 < NUM_AUTHOR) == selfA;
        bool s3 = (n3 < NUM_AUTHOR) == selfA;
        __half2 h0 = *((const __half2*)(g_proj + (size_t)n0 * PSTR + (s0 ? 320 : 640)) + tid);
        __half2 h1 = *((const __half2*)(g_proj + (size_t)n1 * PSTR + (s1 ? 320 : 640)) + tid);
        __half2 h2 = *((const __half2*)(g_proj + (size_t)n2 * PSTR + (s2 ? 320 : 640)) + tid);
        __half2 h3 = *((const __half2*)(g_proj + (size_t)n3 * PSTR + (s3 ? 320 : 640)) + tid);
        float2 f0 = __half22float2(h0);
        float2 f1 = __half22float2(h1);
        float2 f2 = __half22float2(h2);
        float2 f3 = __half22float2(h3);
        if (s0) { a1.x += f0.x; a1.y += f0.y; } else { a2.x += f0.x; a2.y += f0.y; }
        if (s1) { a1.x += f1.x; a1.y += f1.y; } else { a2.x += f1.x; a2.y += f1.y; }
        if (s2) { a1.x += f2.x; a1.y += f2.y; } else { a2.x += f2.x; a2.y += f2.y; }
        if (s3) { a1.x += f3.x; a1.y += f3.y; } else { a2.x += f3.x; a2.y += f3.y; }
        c1 += (int)s0 + (int)s1 + (int)s2 + (int)s3;
    }
    for (; e < end; e++) {
        int n = neighbors[e];
        bool s = (n < NUM_AUTHOR) == selfA;
        __half2 h = *((const __half2*)(g_proj + (size_t)n * PSTR + (s ? 320 : 640)) + tid);
        float2 f = __half22float2(h);
        if (s) { a1.x += f.x; a1.y += f.y; } else { a2.x += f.x; a2.y += f.y; }
        c1 += (int)s;
    }

    if (tid * 2 < DIM) {
        int tot = end - start;
        int c2 = tot - c1;
        float2 t1, t2;
        if (c1 > 0) { float r = 1.0f / (float)c1; t1.x = a1.x * r; t1.y = a1.y * r; }
        else        { t1.x = g_rsB[2 * tid];      t1.y = g_rsB[2 * tid + 1]; }
        if (c2 > 0) { float r = 1.0f / (float)c2; t2.x = a2.x * r; t2.y = a2.y * r; }
        else        { t2.x = g_rsC[2 * tid];      t2.y = g_rsC[2 * tid + 1]; }

        __half2 sh = *((const __half2*)(g_proj + (size_t)node * PSTR) + tid);
        float2 sf = __half22float2(sh);
        float2 bb = *(const float2*)(b1 + 2 * tid);
        float2 o;
        o.x = sf.x + t1.x + t2.x + bb.x;
        o.y = sf.y + t1.y + t2.y + bb.y;
        *(float2*)(out + (size_t)b * DIM + 2 * tid) = o;
    }
}

// ---------------------------------------------------------------------------
extern "C" void kernel_launch(void* const* d_in, const int* in_sizes, int n_in,
                              void* d_out, int out_size) {
    const int*   nodes     = (const int*)d_in[0];
    const int*   seg       = (const int*)d_in[1];
    const int*   neighbors = (const int*)d_in[2];
    const float* emb       = (const float*)d_in[3];
    const float* W1        = (const float*)d_in[4];
    const float* b1        = (const float*)d_in[5];
    float*       out       = (float*)d_out;

    offsets_kernel<<<(NB + 1 + 255) / 256, 256>>>(seg);
    apad_kernel<<<MPAD, 320>>>(emb);
    wcat_kernel<<<NPADC, 320>>>(W1);
    rowsum_kernel<<<1, 320>>>(W1);
    dim3 ggrid(NPADC / BN, MPAD / BM);   // (15, 228), x-fast shares A via L2
    proj_gemm_kernel<<<ggrid, 128>>>();
    agg_kernel<<<NB, 160>>>(nodes, neighbors, b1, out);
}

// round 6
// speedup vs baseline: 1.4634x; 1.2107x over previous
#include <cuda_runtime.h>
#include <cuda_fp16.h>
#include <cstdint>

// Problem constants
#define NUM_AUTHOR 16604
#define NUM_NODES  29059
#define DIM        300
#define NB         32768
#define NE         1048576

// GEMM shape: proj = emb[29059,300] @ Wcat[960,300]^T  (padded M=29184, K=320)
#define MPAD  29184        // 228 * 128
#define KA    320          // padded K for wcat rows
#define NPADC 960          // 3 sections x 320 cols
#define PSTR  960          // proj row stride (halves)

// Scratch (device globals; allocation-free rule)
__device__ float  g_wcat[(size_t)NPADC * KA];    // tf32-rounded, remapped W1
__device__ __half g_proj[(size_t)MPAD * PSTR];   // projected table, fp16 (56 MB)
__device__ float  g_rsB[DIM];                    // rowsum of Wb (empty-type-1 fallback)
__device__ float  g_rsC[DIM];                    // rowsum of Wc (empty-type-2 fallback)
__device__ int    g_off[NB + 1];

__device__ __forceinline__ float tf32r(float x) {
    uint32_t u;
    asm("cvt.rna.tf32.f32 %0, %1;" : "=r"(u) : "f"(x));
    return __uint_as_float(u);
}
__device__ __forceinline__ uint32_t tf32u(float x) {
    uint32_t u;
    asm("cvt.rna.tf32.f32 %0, %1;" : "=r"(u) : "f"(x));
    return u;
}

__device__ __forceinline__ void cp_async16(void* sdst, const void* gsrc) {
    uint32_t d = (uint32_t)__cvta_generic_to_shared(sdst);
    asm volatile("cp.async.cg.shared.global [%0], [%1], 16;" :: "r"(d), "l"(gsrc));
}
// zero-fill variant: copies src_size bytes (0 or 16), zero-fills the rest
__device__ __forceinline__ void cp_async16z(void* sdst, const void* gsrc, int sz) {
    uint32_t d = (uint32_t)__cvta_generic_to_shared(sdst);
    asm volatile("cp.async.cg.shared.global [%0], [%1], 16, %2;" :: "r"(d), "l"(gsrc), "r"(sz));
}
#define CP_COMMIT() asm volatile("cp.async.commit_group;")
#define CP_WAIT(n)  asm volatile("cp.async.wait_group %0;" :: "n"(n))

// ---------------------------------------------------------------------------
// Kernel 1: segment offsets via binary search (seg sorted)
// ---------------------------------------------------------------------------
__global__ void offsets_kernel(const int* __restrict__ seg) {
    int i = blockIdx.x * blockDim.x + threadIdx.x;
    if (i > NB) return;
    int lo = 0, hi = NE;
    while (lo < hi) {
        int mid = (lo + hi) >> 1;
        if (seg[mid] < i) lo = mid + 1; else hi = mid;
    }
    g_off[i] = lo;
}

// ---------------------------------------------------------------------------
// Kernel 2: build Wcat [960 x 320]: wcat[s*320+j][k] = tf32(W1[j][s*300+k])
// ---------------------------------------------------------------------------
__global__ void wcat_kernel(const float* __restrict__ W1) {
    int c = blockIdx.x, k = threadIdx.x;       // grid=960, block=320
    int sec = c / 320, j = c - sec * 320;
    float v = 0.0f;
    if (j < DIM && k < DIM) v = tf32r(W1[(size_t)j * (3 * DIM) + sec * DIM + k]);
    g_wcat[(size_t)c * KA + k] = v;
}

// ---------------------------------------------------------------------------
// Kernel 3: parallel fallback rowsums: rsB[j]=sum_k W1[j,300+k], rsC for 600+k
// grid=300, block=64 (warp 0 -> B, warp 1 -> C), shuffle reduce
// ---------------------------------------------------------------------------
__global__ void rowsum_kernel(const float* __restrict__ W1) {
    int j = blockIdx.x;
    int w = threadIdx.x >> 5, lane = threadIdx.x & 31;
    const float* base = W1 + (size_t)j * (3 * DIM) + DIM + w * DIM;
    float s = 0.f;
    for (int k = lane; k < DIM; k += 32) s += base[k];
#pragma unroll
    for (int o = 16; o; o >>= 1) s += __shfl_xor_sync(0xffffffffu, s, o);
    if (lane == 0) {
        if (w == 0) g_rsB[j] = s; else g_rsC[j] = s;
    }
}

// ---------------------------------------------------------------------------
// Kernel 4: GEMM  proj[MPAD,960](fp16) = emb(padded) @ wcat^T
// tf32 mma m16n8k8; BM=128, BN=96, BK=32; 4 warps (2m x 2n), warp tile 64x48
// A loaded DIRECTLY from emb via cp.async zero-fill; tf32 cvt on A-fragments.
// XOR-swizzled dynamic smem (56 KB), double buffered.
// ---------------------------------------------------------------------------
#define BM 128
#define BN 96
#define BK 32
#define NT (KA / BK)       // 10
#define A_BUF (BM * BK)    // 4096 floats
#define B_BUF (BN * BK)    // 3072 floats
#define GEMM_SMEM ((2 * A_BUF + 2 * B_BUF) * 4)   // 57344 bytes

__device__ __forceinline__ void load_tiles(const float* __restrict__ emb,
                                           const float* __restrict__ Bg,
                                           float* sA, float* sB,
                                           int bmBase, int kt, int tid) {
    int colBase = kt * BK;
#pragma unroll
    for (int i = 0; i < 8; i++) {              // A: 128x32 = 1024 float4
        int lin = tid + i * 128;
        int row = lin >> 3, c4 = lin & 7;
        int gr  = bmBase + row;
        int col = colBase + c4 * 4;
        bool valid = (gr < NUM_NODES) && (col < DIM);
        const float* src = valid ? emb + (size_t)gr * DIM + col : emb;
        int scol = (c4 * 4) ^ ((row & 7) << 2);
        cp_async16z(&sA[row * BK + scol], src, valid ? 16 : 0);
    }
#pragma unroll
    for (int i = 0; i < 6; i++) {              // B: 96x32 = 768 float4
        int lin = tid + i * 128;
        int row = lin >> 3, c4 = lin & 7;
        int scol = (c4 * 4) ^ ((row & 7) << 2);
        cp_async16(&sB[row * BK + scol], Bg + (size_t)row * KA + colBase + c4 * 4);
    }
}

__global__ void __launch_bounds__(128) proj_gemm_kernel(const float* __restrict__ emb) {
    extern __shared__ float sm[];
    float* sA = sm;                 // [2][BM][BK]
    float* sB = sm + 2 * A_BUF;     // [2][BN][BK]

    int bn = blockIdx.x;      // 0..9
    int bm = blockIdx.y;      // 0..227
    int tid = threadIdx.x;
    int warp = tid >> 5, lane = tid & 31;
    int wm = warp & 1, wn = warp >> 1;
    int gid = lane >> 2, tig = lane & 3;

    int bmBase = bm * BM;
    const float* Bg = g_wcat + (size_t)(bn * BN) * KA;

    float c[4][6][4];
#pragma unroll
    for (int mt = 0; mt < 4; mt++)
#pragma unroll
        for (int nt = 0; nt < 6; nt++)
#pragma unroll
            for (int i = 0; i < 4; i++) c[mt][nt][i] = 0.f;

    load_tiles(emb, Bg, sA, sB, bmBase, 0, tid);
    CP_COMMIT();

    for (int kt = 0; kt < NT; kt++) {
        int buf = kt & 1;
        if (kt + 1 < NT) {
            load_tiles(emb, Bg, sA + (buf ^ 1) * A_BUF, sB + (buf ^ 1) * B_BUF,
                       bmBase, kt + 1, tid);
            CP_COMMIT();
            CP_WAIT(1);
        } else {
            CP_WAIT(0);
        }
        __syncthreads();

        const float* Ab = sA + buf * A_BUF;
        const float* Bb = sB + buf * B_BUF;

#pragma unroll
        for (int ks = 0; ks < 4; ks++) {
            int k0 = ks * 8;
            uint32_t a[4][4], bfr[6][2];
#pragma unroll
            for (int mt = 0; mt < 4; mt++) {
                int r0 = wm * 64 + mt * 16 + gid;
                int x = (r0 & 7) << 2;           // (r0+8)&7 == r0&7
                a[mt][0] = tf32u(Ab[r0 * BK + ((k0 + tig) ^ x)]);
                a[mt][1] = tf32u(Ab[(r0 + 8) * BK + ((k0 + tig) ^ x)]);
                a[mt][2] = tf32u(Ab[r0 * BK + ((k0 + tig + 4) ^ x)]);
                a[mt][3] = tf32u(Ab[(r0 + 8) * BK + ((k0 + tig + 4) ^ x)]);
            }
#pragma unroll
            for (int nt = 0; nt < 6; nt++) {
                int n = wn * 48 + nt * 8 + gid;
                int x = (n & 7) << 2;
                bfr[nt][0] = __float_as_uint(Bb[n * BK + ((k0 + tig) ^ x)]);
                bfr[nt][1] = __float_as_uint(Bb[n * BK + ((k0 + tig + 4) ^ x)]);
            }
#pragma unroll
            for (int mt = 0; mt < 4; mt++)
#pragma unroll
                for (int nt = 0; nt < 6; nt++) {
                    asm volatile(
                        "mma.sync.aligned.m16n8k8.row.col.f32.tf32.tf32.f32 "
                        "{%0,%1,%2,%3},{%4,%5,%6,%7},{%8,%9},{%0,%1,%2,%3};"
                        : "+f"(c[mt][nt][0]), "+f"(c[mt][nt][1]),
                          "+f"(c[mt][nt][2]), "+f"(c[mt][nt][3])
                        : "r"(a[mt][0]), "r"(a[mt][1]), "r"(a[mt][2]), "r"(a[mt][3]),
                          "r"(bfr[nt][0]), "r"(bfr[nt][1]));
                }
        }
        __syncthreads();
    }

    // Epilogue: fp16 store (bias added later in agg)
#pragma unroll
    for (int mt = 0; mt < 4; mt++) {
#pragma unroll
        for (int nt = 0; nt < 6; nt++) {
            int gm = bmBase + wm * 64 + mt * 16 + gid;
            int gn = bn * BN + wn * 48 + nt * 8 + tig * 2;
            __half2 h0 = __floats2half2_rn(c[mt][nt][0], c[mt][nt][1]);
            __half2 h1 = __floats2half2_rn(c[mt][nt][2], c[mt][nt][3]);
            *(__half2*)(g_proj + (size_t)gm * PSTR + gn) = h0;
            *(__half2*)(g_proj + (size_t)(gm + 8) * PSTR + gn) = h1;
        }
    }
}

// ---------------------------------------------------------------------------
// Kernel 5: aggregation over fp16 projected table, writes final out
// block = one query node, 160 threads (thread = 2 dims via half2)
// proj row layout: [projA: 0..299][pad][projB: 320..619][pad][projC: 640..939]
// ---------------------------------------------------------------------------
__global__ void __launch_bounds__(160) agg_kernel(
    const int* __restrict__ nodes,
    const int* __restrict__ neighbors,
    const float* __restrict__ b1,
    float* __restrict__ out)
{
    int b = blockIdx.x;
    int tid = threadIdx.x;
    int start = g_off[b];
    int end   = g_off[b + 1];
    int node  = nodes[b];
    bool selfA = node < NUM_AUTHOR;

    float2 a1 = {0.f, 0.f}, a2 = {0.f, 0.f};
    int c1 = 0;

    int e = start;
    for (; e + 4 <= end; e += 4) {
        int n0 = neighbors[e];
        int n1 = neighbors[e + 1];
        int n2 = neighbors[e + 2];
        int n3 = neighbors[e + 3];
        bool s0 = (n0 < NUM_AUTHOR) == selfA;
        bool s1 = (n1 < NUM_AUTHOR) == selfA;
        bool s2 = (n2 < NUM_AUTHOR) == selfA;
        bool s3 = (n3 < NUM_AUTHOR) == selfA;
        __half2 h0 = *((const __half2*)(g_proj + (size_t)n0 * PSTR + (s0 ? 320 : 640)) + tid);
        __half2 h1 = *((const __half2*)(g_proj + (size_t)n1 * PSTR + (s1 ? 320 : 640)) + tid);
        __half2 h2 = *((const __half2*)(g_proj + (size_t)n2 * PSTR + (s2 ? 320 : 640)) + tid);
        __half2 h3 = *((const __half2*)(g_proj + (size_t)n3 * PSTR + (s3 ? 320 : 640)) + tid);
        float2 f0 = __half22float2(h0);
        float2 f1 = __half22float2(h1);
        float2 f2 = __half22float2(h2);
        float2 f3 = __half22float2(h3);
        if (s0) { a1.x += f0.x; a1.y += f0.y; } else { a2.x += f0.x; a2.y += f0.y; }
        if (s1) { a1.x += f1.x; a1.y += f1.y; } else { a2.x += f1.x; a2.y += f1.y; }
        if (s2) { a1.x += f2.x; a1.y += f2.y; } else { a2.x += f2.x; a2.y += f2.y; }
        if (s3) { a1.x += f3.x; a1.y += f3.y; } else { a2.x += f3.x; a2.y += f3.y; }
        c1 += (int)s0 + (int)s1 + (int)s2 + (int)s3;
    }
    for (; e < end; e++) {
        int n = neighbors[e];
        bool s = (n < NUM_AUTHOR) == selfA;
        __half2 h = *((const __half2*)(g_proj + (size_t)n * PSTR + (s ? 320 : 640)) + tid);
        float2 f = __half22float2(h);
        if (s) { a1.x += f.x; a1.y += f.y; } else { a2.x += f.x; a2.y += f.y; }
        c1 += (int)s;
    }

    if (tid * 2 < DIM) {
        int tot = end - start;
        int c2 = tot - c1;
        float2 t1, t2;
        if (c1 > 0) { float r = 1.0f / (float)c1; t1.x = a1.x * r; t1.y = a1.y * r; }
        else        { t1.x = g_rsB[2 * tid];      t1.y = g_rsB[2 * tid + 1]; }
        if (c2 > 0) { float r = 1.0f / (float)c2; t2.x = a2.x * r; t2.y = a2.y * r; }
        else        { t2.x = g_rsC[2 * tid];      t2.y = g_rsC[2 * tid + 1]; }

        __half2 sh = *((const __half2*)(g_proj + (size_t)node * PSTR) + tid);
        float2 sf = __half22float2(sh);
        float2 bb = *(const float2*)(b1 + 2 * tid);
        float2 o;
        o.x = sf.x + t1.x + t2.x + bb.x;
        o.y = sf.y + t1.y + t2.y + bb.y;
        *(float2*)(out + (size_t)b * DIM + 2 * tid) = o;
    }
}

// ---------------------------------------------------------------------------
extern "C" void kernel_launch(void* const* d_in, const int* in_sizes, int n_in,
                              void* d_out, int out_size) {
    const int*   nodes     = (const int*)d_in[0];
    const int*   seg       = (const int*)d_in[1];
    const int*   neighbors = (const int*)d_in[2];
    const float* emb       = (const float*)d_in[3];
    const float* W1        = (const float*)d_in[4];
    const float* b1        = (const float*)d_in[5];
    float*       out       = (float*)d_out;

    cudaFuncSetAttribute(proj_gemm_kernel,
                         cudaFuncAttributeMaxDynamicSharedMemorySize, GEMM_SMEM);

    offsets_kernel<<<(NB + 1 + 255) / 256, 256>>>(seg);
    wcat_kernel<<<NPADC, 320>>>(W1);
    rowsum_kernel<<<DIM, 64>>>(W1);
    dim3 ggrid(NPADC / BN, MPAD / BM);   // (10, 228), x-fast shares A via L2
    proj_gemm_kernel<<<ggrid, 128, GEMM_SMEM>>>(emb);
    agg_kernel<<<NB, 160>>>(nodes, neighbors, b1, out);
}